// round 2
// baseline (speedup 1.0000x reference)
#include <cuda_runtime.h>

// Per-row cosine similarity, persistent grid-stride version.
//   out[i] = dot(q_i, d_i) / (||q_i|| * ||d_i||),  N = 262144 rows, D = 256 fp32.
// HBM-bound streaming (513 MB total). One warp per row per iteration; grid is
// exactly one wave (152 SMs x 8 blocks x 8 warps = 9728 warps), each warp
// strides over rows. Removes the ~27 wave transitions of the naive launch.

#define DIM 256
#define ROW_F4 (DIM / 4)   // 64 float4 per row

__global__ __launch_bounds__(256, 8)
void cosine_rows_persistent(const float4* __restrict__ q,
                            const float4* __restrict__ d,
                            float* __restrict__ out,
                            int n_rows) {
    const int lane = threadIdx.x & 31;
    const int warp_global = (int)((blockIdx.x * blockDim.x + threadIdx.x) >> 5);
    const int n_warps = (int)((gridDim.x * blockDim.x) >> 5);

    for (int row = warp_global; row < n_rows; row += n_warps) {
        const long long base = (long long)row * ROW_F4;

        // 4 independent 128B-coalesced loads, front-batched.
        float4 q0 = __ldg(&q[base + lane]);
        float4 q1 = __ldg(&q[base + lane + 32]);
        float4 d0 = __ldg(&d[base + lane]);
        float4 d1 = __ldg(&d[base + lane + 32]);

        float qq = q0.x * q0.x + q0.y * q0.y + q0.z * q0.z + q0.w * q0.w
                 + q1.x * q1.x + q1.y * q1.y + q1.z * q1.z + q1.w * q1.w;
        float dd = d0.x * d0.x + d0.y * d0.y + d0.z * d0.z + d0.w * d0.w
                 + d1.x * d1.x + d1.y * d1.y + d1.z * d1.z + d1.w * d1.w;
        float qd = q0.x * d0.x + q0.y * d0.y + q0.z * d0.z + q0.w * d0.w
                 + q1.x * d1.x + q1.y * d1.y + q1.z * d1.z + q1.w * d1.w;

        #pragma unroll
        for (int off = 16; off > 0; off >>= 1) {
            qq += __shfl_xor_sync(0xFFFFFFFFu, qq, off);
            dd += __shfl_xor_sync(0xFFFFFFFFu, dd, off);
            qd += __shfl_xor_sync(0xFFFFFFFFu, qd, off);
        }

        if (lane == 0) {
            out[row] = qd * rsqrtf(qq * dd);
        }
    }
}

extern "C" void kernel_launch(void* const* d_in, const int* in_sizes, int n_in,
                              void* d_out, int out_size) {
    const float4* q = (const float4*)d_in[0];
    const float4* d = (const float4*)d_in[1];
    float* out = (float*)d_out;

    const int n_rows = in_sizes[0] / DIM;  // 262144

    // One resident wave: 152 SMs x 8 blocks/SM (28 regs, 256 thr -> 8 CTAs fit).
    const int threads = 256;
    const int blocks = 152 * 8;

    cosine_rows_persistent<<<blocks, threads>>>(q, d, out, n_rows);
}

// round 3
// speedup vs baseline: 1.0296x; 1.0296x over previous
#include <cuda_runtime.h>

// Per-row cosine similarity:
//   out[i] = dot(q_i, d_i) / (||q_i|| * ||d_i||),  N = 262144 rows, D = 256 fp32.
// HBM-bound streaming. Naive (non-persistent) launch; TWO rows per warp:
// 8 independent 128B-coalesced loads front-batched per warp, two independent
// reduction chains interleaved for ILP.

#define DIM 256
#define ROW_F4 (DIM / 4)   // 64 float4 per row

__global__ __launch_bounds__(256)
void cosine_rows2_kernel(const float4* __restrict__ q,
                         const float4* __restrict__ d,
                         float* __restrict__ out,
                         int n_rows) {
    const int warp_in_block = threadIdx.x >> 5;
    const int lane = threadIdx.x & 31;
    // Each warp owns two consecutive rows.
    const int row0 = (blockIdx.x * (blockDim.x >> 5) + warp_in_block) * 2;
    if (row0 >= n_rows) return;

    const long long baseA = (long long)row0 * ROW_F4;
    const long long baseB = baseA + ROW_F4;

    // 8 independent loads, all issued before any use.
    float4 qa0 = __ldg(&q[baseA + lane]);
    float4 qa1 = __ldg(&q[baseA + lane + 32]);
    float4 da0 = __ldg(&d[baseA + lane]);
    float4 da1 = __ldg(&d[baseA + lane + 32]);
    float4 qb0 = __ldg(&q[baseB + lane]);
    float4 qb1 = __ldg(&q[baseB + lane + 32]);
    float4 db0 = __ldg(&d[baseB + lane]);
    float4 db1 = __ldg(&d[baseB + lane + 32]);

    float qqA = qa0.x*qa0.x + qa0.y*qa0.y + qa0.z*qa0.z + qa0.w*qa0.w
              + qa1.x*qa1.x + qa1.y*qa1.y + qa1.z*qa1.z + qa1.w*qa1.w;
    float ddA = da0.x*da0.x + da0.y*da0.y + da0.z*da0.z + da0.w*da0.w
              + da1.x*da1.x + da1.y*da1.y + da1.z*da1.z + da1.w*da1.w;
    float qdA = qa0.x*da0.x + qa0.y*da0.y + qa0.z*da0.z + qa0.w*da0.w
              + qa1.x*da1.x + qa1.y*da1.y + qa1.z*da1.z + qa1.w*da1.w;

    float qqB = qb0.x*qb0.x + qb0.y*qb0.y + qb0.z*qb0.z + qb0.w*qb0.w
              + qb1.x*qb1.x + qb1.y*qb1.y + qb1.z*qb1.z + qb1.w*qb1.w;
    float ddB = db0.x*db0.x + db0.y*db0.y + db0.z*db0.z + db0.w*db0.w
              + db1.x*db1.x + db1.y*db1.y + db1.z*db1.z + db1.w*db1.w;
    float qdB = qb0.x*db0.x + qb0.y*db0.y + qb0.z*db0.z + qb0.w*db0.w
              + qb1.x*db1.x + qb1.y*db1.y + qb1.z*db1.z + qb1.w*db1.w;

    // Two independent butterfly chains interleave (6 shuffles per stage, ILP).
    #pragma unroll
    for (int off = 16; off > 0; off >>= 1) {
        qqA += __shfl_xor_sync(0xFFFFFFFFu, qqA, off);
        qqB += __shfl_xor_sync(0xFFFFFFFFu, qqB, off);
        ddA += __shfl_xor_sync(0xFFFFFFFFu, ddA, off);
        ddB += __shfl_xor_sync(0xFFFFFFFFu, ddB, off);
        qdA += __shfl_xor_sync(0xFFFFFFFFu, qdA, off);
        qdB += __shfl_xor_sync(0xFFFFFFFFu, qdB, off);
    }

    if (lane == 0) {
        out[row0]     = qdA * rsqrtf(qqA * ddA);
        out[row0 + 1] = qdB * rsqrtf(qqB * ddB);
    }
}

extern "C" void kernel_launch(void* const* d_in, const int* in_sizes, int n_in,
                              void* d_out, int out_size) {
    const float4* q = (const float4*)d_in[0];
    const float4* d = (const float4*)d_in[1];
    float* out = (float*)d_out;

    const int n_rows = in_sizes[0] / DIM;  // 262144

    const int threads = 256;                         // 8 warps
    const int rows_per_block = (threads / 32) * 2;   // 16 rows/block
    const int blocks = (n_rows + rows_per_block - 1) / rows_per_block;  // 16384

    cosine_rows2_kernel<<<blocks, threads>>>(q, d, out, n_rows);
}

// round 7
// speedup vs baseline: 1.0579x; 1.0275x over previous
#include <cuda_runtime.h>

// Per-row cosine similarity:
//   out[i] = dot(q_i, d_i) / (||q_i|| * ||d_i||),  N = 262144 rows, D = 256 fp32.
// HBM-bound streaming at the achieved-BW ceiling (~7 TB/s). R1 shape (1 row per
// warp, 8 warps/block, naive launch) + shared-memory output staging so each
// block issues ONE coalesced 32B store instead of 8 scattered 4B stores
// (cuts write DRAM traffic ~8MB -> ~2MB). Loads use streaming (.cs) hint:
// data is touched exactly once.

#define DIM 256
#define ROW_F4 (DIM / 4)   // 64 float4 per row

__global__ __launch_bounds__(256, 8)
void cosine_rows_stg_kernel(const float4* __restrict__ q,
                            const float4* __restrict__ d,
                            float* __restrict__ out,
                            int n_rows) {
    __shared__ float s_res[8];

    const int warp_in_block = threadIdx.x >> 5;
    const int lane = threadIdx.x & 31;
    const int row = blockIdx.x * (blockDim.x >> 5) + warp_in_block;

    const long long base = (long long)row * ROW_F4;

    // 4 independent 128B-coalesced streaming loads.
    float4 q0 = __ldcs(&q[base + lane]);
    float4 q1 = __ldcs(&q[base + lane + 32]);
    float4 d0 = __ldcs(&d[base + lane]);
    float4 d1 = __ldcs(&d[base + lane + 32]);

    float qq = q0.x * q0.x + q0.y * q0.y + q0.z * q0.z + q0.w * q0.w
             + q1.x * q1.x + q1.y * q1.y + q1.z * q1.z + q1.w * q1.w;
    float dd = d0.x * d0.x + d0.y * d0.y + d0.z * d0.z + d0.w * d0.w
             + d1.x * d1.x + d1.y * d1.y + d1.z * d1.z + d1.w * d1.w;
    float qd = q0.x * d0.x + q0.y * d0.y + q0.z * d0.z + q0.w * d0.w
             + q1.x * d1.x + q1.y * d1.y + q1.z * d1.z + q1.w * d1.w;

    #pragma unroll
    for (int off = 16; off > 0; off >>= 1) {
        qq += __shfl_xor_sync(0xFFFFFFFFu, qq, off);
        dd += __shfl_xor_sync(0xFFFFFFFFu, dd, off);
        qd += __shfl_xor_sync(0xFFFFFFFFu, qd, off);
    }

    if (lane == 0) {
        s_res[warp_in_block] = qd * rsqrtf(qq * dd);
    }
    __syncthreads();

    // One coalesced 32B store per block (lanes 0-7 of warp 0).
    if (threadIdx.x < 8) {
        const int out_base = blockIdx.x * 8;
        if (out_base + (int)threadIdx.x < n_rows) {
            out[out_base + threadIdx.x] = s_res[threadIdx.x];
        }
    }
}

extern "C" void kernel_launch(void* const* d_in, const int* in_sizes, int n_in,
                              void* d_out, int out_size) {
    const float4* q = (const float4*)d_in[0];
    const float4* d = (const float4*)d_in[1];
    float* out = (float*)d_out;

    const int n_rows = in_sizes[0] / DIM;  // 262144 (multiple of 8)

    const int threads = 256;               // 8 warps -> 8 rows per block
    const int rows_per_block = threads / 32;
    const int blocks = (n_rows + rows_per_block - 1) / rows_per_block;  // 32768

    cosine_rows_stg_kernel<<<blocks, threads>>>(q, d, out, n_rows);
}